// round 1
// baseline (speedup 1.0000x reference)
#include <cuda_runtime.h>
#include <math.h>

// Problem dims
#define Bb 8
#define Nn 1024
#define Ss 1024
#define Cc 768
#define Hh_ 12
#define Dd 64
#define SCALE 0.125f

// Scratch (static __device__ — allocation-free per harness rules)
__device__ float g_Q[(long long)Bb * Nn * Cc];            // 6.29M
__device__ float g_K[(long long)Bb * Ss * Cc];
__device__ float g_V[(long long)Bb * Ss * Cc];
__device__ float g_S[(long long)Bb * Hh_ * Nn * Ss];      // 100.66M (scores -> attn in place)
__device__ float g_O[(long long)Bb * Nn * Cc];            // head outputs, [B,N,C] layout

// ---------------------------------------------------------------------------
// NT GEMM: C[m][n] = scale * sum_k A[m*lda+k] * B[n*ldb+k]  (+ bias[n])
// Block tile 64x64, 256 threads, 4x4 per thread, BK=16.
// Batched via blockIdx.z -> (b, h) with separate batch/head strides.
// Requires M%64==0, N%64==0, K%16==0 (holds for all uses here).
// ---------------------------------------------------------------------------
__global__ __launch_bounds__(256)
void gemm_nt(const float* __restrict__ A, const float* __restrict__ B,
             float* __restrict__ C, int Kdim,
             int lda, int ldb, int ldc, int nh,
             long long sAb, long long sAh,
             long long sBb, long long sBh,
             long long sCb, long long sCh,
             float scale, const float* __restrict__ bias)
{
    __shared__ float As[64][17];
    __shared__ float Bs[64][17];

    int bz = blockIdx.z;
    int b = bz / nh;
    int h = bz - b * nh;
    A += (long long)b * sAb + (long long)h * sAh;
    B += (long long)b * sBb + (long long)h * sBh;
    C += (long long)b * sCb + (long long)h * sCh;

    int m0 = blockIdx.y * 64;
    int n0 = blockIdx.x * 64;
    int tid = threadIdx.x;
    int tx = tid & 15;
    int ty = tid >> 4;

    float acc[4][4] = {};

    for (int k0 = 0; k0 < Kdim; k0 += 16) {
        #pragma unroll
        for (int i = 0; i < 4; i++) {
            int e = tid + i * 256;
            int r = e >> 4, c = e & 15;
            As[r][c] = A[(long long)(m0 + r) * lda + k0 + c];
            Bs[r][c] = B[(long long)(n0 + r) * ldb + k0 + c];
        }
        __syncthreads();
        #pragma unroll
        for (int k = 0; k < 16; k++) {
            float a[4], bb[4];
            #pragma unroll
            for (int i = 0; i < 4; i++) a[i] = As[ty * 4 + i][k];
            #pragma unroll
            for (int j = 0; j < 4; j++) bb[j] = Bs[tx * 4 + j][k];
            #pragma unroll
            for (int i = 0; i < 4; i++)
                #pragma unroll
                for (int j = 0; j < 4; j++) acc[i][j] += a[i] * bb[j];
        }
        __syncthreads();
    }

    #pragma unroll
    for (int i = 0; i < 4; i++) {
        int m = m0 + ty * 4 + i;
        #pragma unroll
        for (int j = 0; j < 4; j++) {
            int n = n0 + tx * 4 + j;
            float v = acc[i][j] * scale;
            if (bias) v += bias[n];
            C[(long long)m * ldc + n] = v;
        }
    }
}

// ---------------------------------------------------------------------------
// NN GEMM: C[m][n] = sum_k A[m*lda+k] * B[k*ldb+n]
// Same tiling. Used for attn @ V (M=1024, N=64, K=1024 per (b,h)).
// ---------------------------------------------------------------------------
__global__ __launch_bounds__(256)
void gemm_nn(const float* __restrict__ A, const float* __restrict__ B,
             float* __restrict__ C, int Kdim,
             int lda, int ldb, int ldc, int nh,
             long long sAb, long long sAh,
             long long sBb, long long sBh,
             long long sCb, long long sCh)
{
    __shared__ float As[64][17];
    __shared__ float Bs[16][68];

    int bz = blockIdx.z;
    int b = bz / nh;
    int h = bz - b * nh;
    A += (long long)b * sAb + (long long)h * sAh;
    B += (long long)b * sBb + (long long)h * sBh;
    C += (long long)b * sCb + (long long)h * sCh;

    int m0 = blockIdx.y * 64;
    int n0 = blockIdx.x * 64;
    int tid = threadIdx.x;
    int tx = tid & 15;
    int ty = tid >> 4;

    float acc[4][4] = {};

    for (int k0 = 0; k0 < Kdim; k0 += 16) {
        #pragma unroll
        for (int i = 0; i < 4; i++) {
            int e = tid + i * 256;
            int ra = e >> 4, ca = e & 15;
            As[ra][ca] = A[(long long)(m0 + ra) * lda + k0 + ca];
            int rb = e >> 6, cb = e & 63;
            Bs[rb][cb] = B[(long long)(k0 + rb) * ldb + n0 + cb];
        }
        __syncthreads();
        #pragma unroll
        for (int k = 0; k < 16; k++) {
            float a[4], bb[4];
            #pragma unroll
            for (int i = 0; i < 4; i++) a[i] = As[ty * 4 + i][k];
            #pragma unroll
            for (int j = 0; j < 4; j++) bb[j] = Bs[k][tx * 4 + j];
            #pragma unroll
            for (int i = 0; i < 4; i++)
                #pragma unroll
                for (int j = 0; j < 4; j++) acc[i][j] += a[i] * bb[j];
        }
        __syncthreads();
    }

    #pragma unroll
    for (int i = 0; i < 4; i++) {
        int m = m0 + ty * 4 + i;
        #pragma unroll
        for (int j = 0; j < 4; j++) {
            int n = n0 + tx * 4 + j;
            C[(long long)m * ldc + n] = acc[i][j];
        }
    }
}

// ---------------------------------------------------------------------------
// Row softmax stage: per row of S=1024:
//   lse = logsumexp(scores)
//   logits = attn_weight + scores - lse         -> write to log_attn output
//   attn = softmax(logits)                      -> overwrite scores scratch
// One block per row, 256 threads, 4 elems/thread.
// ---------------------------------------------------------------------------
__device__ __forceinline__ float warpMax(float v) {
    #pragma unroll
    for (int o = 16; o; o >>= 1) v = fmaxf(v, __shfl_xor_sync(0xffffffffu, v, o));
    return v;
}
__device__ __forceinline__ float warpSum(float v) {
    #pragma unroll
    for (int o = 16; o; o >>= 1) v += __shfl_xor_sync(0xffffffffu, v, o);
    return v;
}

__global__ __launch_bounds__(256)
void softmax_rows(const float* __restrict__ scores,
                  const float* __restrict__ aw,
                  float* __restrict__ log_attn,
                  float* __restrict__ attn)
{
    __shared__ float b1[8], b2[8], b3[8], b4[8];
    long long row = blockIdx.x;
    const float* s = scores + row * 1024;
    const float* w = aw + row * 1024;
    float* la = log_attn + row * 1024;
    float* at = attn + row * 1024;

    int tid = threadIdx.x;
    int lane = tid & 31, warp = tid >> 5;

    float x[4], g[4];
    float m1 = -INFINITY;
    #pragma unroll
    for (int i = 0; i < 4; i++) { x[i] = s[tid + i * 256]; m1 = fmaxf(m1, x[i]); }
    m1 = warpMax(m1);
    if (lane == 0) b1[warp] = m1;
    __syncthreads();
    m1 = fmaxf(fmaxf(fmaxf(b1[0], b1[1]), fmaxf(b1[2], b1[3])),
               fmaxf(fmaxf(b1[4], b1[5]), fmaxf(b1[6], b1[7])));

    float sum1 = 0.f;
    #pragma unroll
    for (int i = 0; i < 4; i++) sum1 += expf(x[i] - m1);
    sum1 = warpSum(sum1);
    if (lane == 0) b2[warp] = sum1;
    __syncthreads();
    sum1 = (b2[0] + b2[1]) + (b2[2] + b2[3]) + (b2[4] + b2[5]) + (b2[6] + b2[7]);
    float lse = m1 + logf(sum1);

    float m2 = -INFINITY;
    #pragma unroll
    for (int i = 0; i < 4; i++) {
        g[i] = w[tid + i * 256] + x[i] - lse;
        la[tid + i * 256] = g[i];
        m2 = fmaxf(m2, g[i]);
    }
    m2 = warpMax(m2);
    if (lane == 0) b3[warp] = m2;
    __syncthreads();
    m2 = fmaxf(fmaxf(fmaxf(b3[0], b3[1]), fmaxf(b3[2], b3[3])),
               fmaxf(fmaxf(b3[4], b3[5]), fmaxf(b3[6], b3[7])));

    float sum2 = 0.f;
    #pragma unroll
    for (int i = 0; i < 4; i++) { g[i] = expf(g[i] - m2); sum2 += g[i]; }
    sum2 = warpSum(sum2);
    if (lane == 0) b4[warp] = sum2;
    __syncthreads();
    sum2 = (b4[0] + b4[1]) + (b4[2] + b4[3]) + (b4[4] + b4[5]) + (b4[6] + b4[7]);
    float inv = 1.0f / sum2;
    #pragma unroll
    for (int i = 0; i < 4; i++) at[tid + i * 256] = g[i] * inv;
}

// ---------------------------------------------------------------------------
extern "C" void kernel_launch(void* const* d_in, const int* in_sizes, int n_in,
                              void* d_out, int out_size)
{
    const float* query = (const float*)d_in[0];
    const float* key   = (const float*)d_in[1];
    const float* value = (const float*)d_in[2];
    const float* aw    = (const float*)d_in[3];
    const float* Wq    = (const float*)d_in[4];
    const float* Wk    = (const float*)d_in[5];
    const float* Wv    = (const float*)d_in[6];
    const float* Wo    = (const float*)d_in[7];
    const float* bo    = (const float*)d_in[8];

    float* out = (float*)d_out;                               // [B,N,C]
    float* log_attn = out + (long long)Bb * Nn * Cc;          // [B,H,N,S]

    float *Q, *K, *V, *Sc, *O;
    cudaGetSymbolAddress((void**)&Q,  g_Q);
    cudaGetSymbolAddress((void**)&K,  g_K);
    cudaGetSymbolAddress((void**)&V,  g_V);
    cudaGetSymbolAddress((void**)&Sc, g_S);
    cudaGetSymbolAddress((void**)&O,  g_O);

    dim3 blk(256);

    // 1-3. Projections: [8192,768] = X[8192,768] @ W^T
    dim3 gProj(Cc / 64, (Bb * Nn) / 64, 1);
    gemm_nt<<<gProj, blk>>>(query, Wq, Q, Cc, Cc, Cc, Cc, 1,
                            0, 0, 0, 0, 0, 0, 1.0f, nullptr);
    gemm_nt<<<gProj, blk>>>(key, Wk, K, Cc, Cc, Cc, Cc, 1,
                            0, 0, 0, 0, 0, 0, 1.0f, nullptr);
    gemm_nt<<<gProj, blk>>>(value, Wv, V, Cc, Cc, Cc, Cc, 1,
                            0, 0, 0, 0, 0, 0, 1.0f, nullptr);

    // 4. scores[b,h] = SCALE * Qh @ Kh^T   (per (b,h): 1024x1024x64)
    dim3 gQK(Ss / 64, Nn / 64, Bb * Hh_);
    gemm_nt<<<gQK, blk>>>(Q, K, Sc, Dd, Cc, Cc, Ss, Hh_,
                          (long long)Nn * Cc, Dd,
                          (long long)Ss * Cc, Dd,
                          (long long)Hh_ * Nn * Ss, (long long)Nn * Ss,
                          SCALE, nullptr);

    // 5. softmax rows: lse -> log_attn out -> attn (in place over scores)
    softmax_rows<<<Bb * Hh_ * Nn, blk>>>(Sc, aw, log_attn, Sc);

    // 6. Ohead[b,:,h*64:...] = attn[b,h] @ Vh   (per (b,h): 1024x64x1024)
    dim3 gAV(1, Nn / 64, Bb * Hh_);
    gemm_nn<<<gAV, blk>>>(Sc, V, O, Ss, Ss, Cc, Cc, Hh_,
                          (long long)Hh_ * Nn * Ss, (long long)Nn * Ss,
                          (long long)Ss * Cc, Dd,
                          (long long)Nn * Cc, Dd);

    // 7. out = Ohead @ Wo^T + bo
    gemm_nt<<<gProj, blk>>>(O, Wo, out, Cc, Cc, Cc, Cc, 1,
                            0, 0, 0, 0, 0, 0, 1.0f, bo);
}

// round 3
// speedup vs baseline: 4.5530x; 4.5530x over previous
#include <cuda_runtime.h>
#include <cuda_fp16.h>
#include <cstdint>
#include <math.h>

// Problem dims
#define Bb 8
#define Nn 1024
#define Ss 1024
#define Cc 768
#define Hh_ 12
#define Dd 64
#define SCALEF 0.125f

// ---------------------------------------------------------------------------
// Scratch (static __device__ — allocation-free per harness rules)
// ---------------------------------------------------------------------------
__device__ __half g_q16[(long long)Bb * Nn * Cc];
__device__ __half g_k16[(long long)Bb * Ss * Cc];
__device__ __half g_v16[(long long)Bb * Ss * Cc];
__device__ __half g_Wq16[Cc * Cc];
__device__ __half g_Wk16[Cc * Cc];
__device__ __half g_Wv16[Cc * Cc];
__device__ __half g_Wo16[Cc * Cc];
__device__ __half g_Q16[(long long)Bb * Nn * Cc];
__device__ __half g_K16[(long long)Bb * Ss * Cc];
__device__ __half g_V16[(long long)Bb * Ss * Cc];
__device__ __half g_Vt[(long long)Bb * Cc * Ss];            // [B][C][S]
__device__ float  g_S[(long long)Bb * Hh_ * Nn * Ss];       // fp32 scores
__device__ __half g_A16[(long long)Bb * Hh_ * Nn * Ss];     // fp16 attn probs
__device__ __half g_O16[(long long)Bb * Nn * Cc];           // head outputs

// ---------------------------------------------------------------------------
// PTX helpers
// ---------------------------------------------------------------------------
__device__ __forceinline__ unsigned s2u32(const void* p) {
    return (unsigned)__cvta_generic_to_shared(p);
}
__device__ __forceinline__ void ldsm4(unsigned* r, unsigned addr) {
    asm volatile("ldmatrix.sync.aligned.m8n8.x4.shared.b16 {%0,%1,%2,%3}, [%4];"
                 : "=r"(r[0]), "=r"(r[1]), "=r"(r[2]), "=r"(r[3]) : "r"(addr));
}
__device__ __forceinline__ void ldsm2(unsigned* r, unsigned addr) {
    asm volatile("ldmatrix.sync.aligned.m8n8.x2.shared.b16 {%0,%1}, [%2];"
                 : "=r"(r[0]), "=r"(r[1]) : "r"(addr));
}
__device__ __forceinline__ void mma16816(float* d, const unsigned* a, const unsigned* b) {
    asm volatile("mma.sync.aligned.m16n8k16.row.col.f32.f16.f16.f32 "
                 "{%0,%1,%2,%3}, {%4,%5,%6,%7}, {%8,%9}, {%0,%1,%2,%3};"
                 : "+f"(d[0]), "+f"(d[1]), "+f"(d[2]), "+f"(d[3])
                 : "r"(a[0]), "r"(a[1]), "r"(a[2]), "r"(a[3]), "r"(b[0]), "r"(b[1]));
}

// Epilogue pair-store: overloads resolve per output type (no constexpr-if).
__device__ __forceinline__ void store2(__half* C, long long off, float v0, float v1) {
    __half2* p = (__half2*)(C + off);
    *p = __floats2half2_rn(v0, v1);
}
__device__ __forceinline__ void store2(float* C, long long off, float v0, float v1) {
    float2* p = (float2*)(C + off);
    *p = make_float2(v0, v1);
}

// ---------------------------------------------------------------------------
// fp16 NT GEMM on tensor cores.
// C[m][n] = scale * sum_k A[m][k]*B[n][k]  (+ bias[n] when BIAS)
// BM=128, BK=32. BN = 128 or 64. 256 threads = 8 warps (4m x 2n).
// ---------------------------------------------------------------------------
template<int BN, typename OutT, bool BIAS>
__global__ __launch_bounds__(256)
void hgemm_nt(const __half* __restrict__ A, const __half* __restrict__ B,
              OutT* __restrict__ C, int Kdim,
              int lda, int ldb, int ldc, int nh,
              long long sAb, long long sAh,
              long long sBb, long long sBh,
              long long sCb, long long sCh,
              float scale, const float* __restrict__ bias)
{
    const int BM = 128;
    const int LDSW = 40;                 // 32 k-halves + 8 pad
    const int WN = BN / 2;               // warp n-extent
    const int NT = WN / 8;               // n8-tiles per warp

    __shared__ alignas(16) __half As[2][BM * LDSW];
    __shared__ alignas(16) __half Bs[2][BN * LDSW];

    int bz = blockIdx.z;
    int b = bz / nh;
    int h = bz - b * nh;
    A += (long long)b * sAb + (long long)h * sAh;
    B += (long long)b * sBb + (long long)h * sBh;
    C += (long long)b * sCb + (long long)h * sCh;

    int m0 = blockIdx.y * BM;
    int n0 = blockIdx.x * BN;
    int tid = threadIdx.x;
    int lane = tid & 31;
    int w = tid >> 5;
    int wm = w & 3;
    int wn = w >> 2;

    // global-load assignment: row = tid>>2, 16B chunk = tid&3
    int grow = tid >> 2;
    int gchk = tid & 3;
    const __half* gA0 = A + (long long)(m0 + grow) * lda + gchk * 8;
    const __half* gA1 = gA0 + 64ll * lda;
    const __half* gB0 = B + (long long)(n0 + grow) * ldb + gchk * 8;
    const __half* gB1 = gB0 + 64ll * ldb;   // used only when BN==128

    uint4 ra0, ra1, rb0, rb1;
    int ssA = grow * LDSW + gchk * 8;

    // ldmatrix per-lane base offsets (in half units)
    int aBase = (wm * 32 + (lane & 15)) * LDSW + (lane >> 4) * 8;
    int bBase = (wn * WN + (lane & 7)) * LDSW + ((lane >> 3) & 1) * 8;
    unsigned asu0 = s2u32(&As[0][0]);
    unsigned asu1 = s2u32(&As[1][0]);
    unsigned bsu0 = s2u32(&Bs[0][0]);
    unsigned bsu1 = s2u32(&Bs[1][0]);

    float acc[2][NT][4];
    #pragma unroll
    for (int i = 0; i < 2; i++)
        #pragma unroll
        for (int j = 0; j < NT; j++) {
            acc[i][j][0] = 0.f; acc[i][j][1] = 0.f;
            acc[i][j][2] = 0.f; acc[i][j][3] = 0.f;
        }

    // prologue: stage tile 0
    ra0 = *(const uint4*)(gA0);
    ra1 = *(const uint4*)(gA1);
    rb0 = *(const uint4*)(gB0);
    if (BN == 128) rb1 = *(const uint4*)(gB1);
    *(uint4*)&As[0][ssA] = ra0;
    *(uint4*)&As[0][ssA + 64 * LDSW] = ra1;
    *(uint4*)&Bs[0][ssA] = rb0;
    if (BN == 128) *(uint4*)&Bs[0][ssA + 64 * LDSW] = rb1;
    __syncthreads();

    int nk = Kdim >> 5;
    for (int kt = 0; kt < nk; kt++) {
        int cur = kt & 1;
        unsigned asu = cur ? asu1 : asu0;
        unsigned bsu = cur ? bsu1 : bsu0;
        if (kt + 1 < nk) {
            int k0 = (kt + 1) << 5;
            ra0 = *(const uint4*)(gA0 + k0);
            ra1 = *(const uint4*)(gA1 + k0);
            rb0 = *(const uint4*)(gB0 + k0);
            if (BN == 128) rb1 = *(const uint4*)(gB1 + k0);
        }
        #pragma unroll
        for (int kk = 0; kk < 2; kk++) {
            unsigned af[2][4];
            unsigned bf[NT][2];
            #pragma unroll
            for (int mt = 0; mt < 2; mt++)
                ldsm4(af[mt], asu + 2u * (unsigned)(aBase + mt * 16 * LDSW + kk * 16));
            #pragma unroll
            for (int nt = 0; nt < NT; nt++)
                ldsm2(bf[nt], bsu + 2u * (unsigned)(bBase + nt * 8 * LDSW + kk * 16));
            #pragma unroll
            for (int mt = 0; mt < 2; mt++)
                #pragma unroll
                for (int nt = 0; nt < NT; nt++)
                    mma16816(acc[mt][nt], af[mt], bf[nt]);
        }
        if (kt + 1 < nk) {
            int nxt = cur ^ 1;
            unsigned asn = nxt ? asu1 : asu0;
            unsigned bsn = nxt ? bsu1 : bsu0;
            __half* Asn = (__half*)&As[nxt][0];
            __half* Bsn = (__half*)&Bs[nxt][0];
            (void)asn; (void)bsn;
            *(uint4*)&Asn[ssA] = ra0;
            *(uint4*)&Asn[ssA + 64 * LDSW] = ra1;
            *(uint4*)&Bsn[ssA] = rb0;
            if (BN == 128) *(uint4*)&Bsn[ssA + 64 * LDSW] = rb1;
            __syncthreads();
        }
    }

    // epilogue
    #pragma unroll
    for (int mt = 0; mt < 2; mt++) {
        int r0 = m0 + wm * 32 + mt * 16 + (lane >> 2);
        #pragma unroll
        for (int nt = 0; nt < NT; nt++) {
            int c0 = n0 + wn * WN + nt * 8 + (lane & 3) * 2;
            float v0 = acc[mt][nt][0] * scale;
            float v1 = acc[mt][nt][1] * scale;
            float v2 = acc[mt][nt][2] * scale;
            float v3 = acc[mt][nt][3] * scale;
            if (BIAS) {
                float bc0 = bias[c0];
                float bc1 = bias[c0 + 1];
                v0 += bc0; v1 += bc1; v2 += bc0; v3 += bc1;
            }
            store2(C, (long long)r0 * ldc + c0, v0, v1);
            store2(C, (long long)(r0 + 8) * ldc + c0, v2, v3);
        }
    }
}

// ---------------------------------------------------------------------------
// fp32 -> fp16 conversion (element count multiple of 4; n4 = count/4)
// ---------------------------------------------------------------------------
__global__ __launch_bounds__(256)
void f2h(const float* __restrict__ in, __half* __restrict__ out, int n4)
{
    int i = blockIdx.x * 256 + threadIdx.x;
    if (i >= n4) return;
    float4 v = ((const float4*)in)[i];
    __half2* o = (__half2*)out + 2 * i;
    o[0] = __floats2half2_rn(v.x, v.y);
    o[1] = __floats2half2_rn(v.z, v.w);
}

// ---------------------------------------------------------------------------
// Transpose V16 [B][S][C] -> Vt [B][C][S]
// ---------------------------------------------------------------------------
__global__ __launch_bounds__(256)
void transpose_v(const __half* __restrict__ in, __half* __restrict__ out)
{
    __shared__ __half tile[32][33];
    int b = blockIdx.z;
    int c0 = blockIdx.x * 32;
    int s0 = blockIdx.y * 32;
    int tx = threadIdx.x;
    int ty = threadIdx.y;
    const __half* ip = in + (long long)b * Ss * Cc;
    __half* op = out + (long long)b * Cc * Ss;
    #pragma unroll
    for (int j = 0; j < 32; j += 8)
        tile[ty + j][tx] = ip[(long long)(s0 + ty + j) * Cc + c0 + tx];
    __syncthreads();
    #pragma unroll
    for (int j = 0; j < 32; j += 8)
        op[(long long)(c0 + ty + j) * Ss + s0 + tx] = tile[tx][ty + j];
}

// ---------------------------------------------------------------------------
// Row softmax: per row of S=1024:
//   lse = logsumexp(scores); logits = aw + scores - lse -> log_attn (fp32)
//   attn = softmax(logits) -> fp16
// ---------------------------------------------------------------------------
__device__ __forceinline__ float warpMax(float v) {
    #pragma unroll
    for (int o = 16; o; o >>= 1) v = fmaxf(v, __shfl_xor_sync(0xffffffffu, v, o));
    return v;
}
__device__ __forceinline__ float warpSum(float v) {
    #pragma unroll
    for (int o = 16; o; o >>= 1) v += __shfl_xor_sync(0xffffffffu, v, o);
    return v;
}

__global__ __launch_bounds__(256)
void softmax_rows(const float* __restrict__ scores,
                  const float* __restrict__ aw,
                  float* __restrict__ log_attn,
                  __half* __restrict__ attn)
{
    __shared__ float redA[8];
    __shared__ float redB[8];
    __shared__ float redC[8];
    __shared__ float redD[8];

    long long row = blockIdx.x;
    const float4* s4 = (const float4*)(scores + row * 1024);
    const float4* w4 = (const float4*)(aw + row * 1024);
    float4* la4 = (float4*)(log_attn + row * 1024);
    __half2* at2 = (__half2*)(attn + row * 1024);

    int tid = threadIdx.x;
    int lane = tid & 31;
    int warp = tid >> 5;

    float4 x = s4[tid];
    float m1 = fmaxf(fmaxf(x.x, x.y), fmaxf(x.z, x.w));
    m1 = warpMax(m1);
    if (lane == 0) redA[warp] = m1;
    __syncthreads();
    m1 = fmaxf(fmaxf(fmaxf(redA[0], redA[1]), fmaxf(redA[2], redA[3])),
               fmaxf(fmaxf(redA[4], redA[5]), fmaxf(redA[6], redA[7])));

    float sum1 = expf(x.x - m1) + expf(x.y - m1) + expf(x.z - m1) + expf(x.w - m1);
    sum1 = warpSum(sum1);
    if (lane == 0) redB[warp] = sum1;
    __syncthreads();
    sum1 = (redB[0] + redB[1]) + (redB[2] + redB[3])
         + (redB[4] + redB[5]) + (redB[6] + redB[7]);
    float lse = m1 + logf(sum1);

    float4 ww = w4[tid];
    float4 g;
    g.x = ww.x + x.x - lse;
    g.y = ww.y + x.y - lse;
    g.z = ww.z + x.z - lse;
    g.w = ww.w + x.w - lse;
    la4[tid] = g;

    float m2 = fmaxf(fmaxf(g.x, g.y), fmaxf(g.z, g.w));
    m2 = warpMax(m2);
    if (lane == 0) redC[warp] = m2;
    __syncthreads();
    m2 = fmaxf(fmaxf(fmaxf(redC[0], redC[1]), fmaxf(redC[2], redC[3])),
               fmaxf(fmaxf(redC[4], redC[5]), fmaxf(redC[6], redC[7])));

    float e0 = expf(g.x - m2);
    float e1 = expf(g.y - m2);
    float e2 = expf(g.z - m2);
    float e3 = expf(g.w - m2);
    float sum2 = (e0 + e1) + (e2 + e3);
    sum2 = warpSum(sum2);
    if (lane == 0) redD[warp] = sum2;
    __syncthreads();
    sum2 = (redD[0] + redD[1]) + (redD[2] + redD[3])
         + (redD[4] + redD[5]) + (redD[6] + redD[7]);
    float inv = 1.0f / sum2;
    at2[2 * tid]     = __floats2half2_rn(e0 * inv, e1 * inv);
    at2[2 * tid + 1] = __floats2half2_rn(e2 * inv, e3 * inv);
}

// ---------------------------------------------------------------------------
extern "C" void kernel_launch(void* const* d_in, const int* in_sizes, int n_in,
                              void* d_out, int out_size)
{
    const float* query = (const float*)d_in[0];
    const float* key   = (const float*)d_in[1];
    const float* value = (const float*)d_in[2];
    const float* aw    = (const float*)d_in[3];
    const float* Wq    = (const float*)d_in[4];
    const float* Wk    = (const float*)d_in[5];
    const float* Wv    = (const float*)d_in[6];
    const float* Wo    = (const float*)d_in[7];
    const float* bo    = (const float*)d_in[8];

    float* out = (float*)d_out;                               // [B,N,C]
    float* log_attn = out + (long long)Bb * Nn * Cc;          // [B,H,N,S]

    __half *q16, *k16, *v16, *Wq16, *Wk16, *Wv16, *Wo16;
    __half *Q16, *K16, *V16, *Vt, *A16, *O16;
    float* Sc;
    cudaGetSymbolAddress((void**)&q16,  g_q16);
    cudaGetSymbolAddress((void**)&k16,  g_k16);
    cudaGetSymbolAddress((void**)&v16,  g_v16);
    cudaGetSymbolAddress((void**)&Wq16, g_Wq16);
    cudaGetSymbolAddress((void**)&Wk16, g_Wk16);
    cudaGetSymbolAddress((void**)&Wv16, g_Wv16);
    cudaGetSymbolAddress((void**)&Wo16, g_Wo16);
    cudaGetSymbolAddress((void**)&Q16,  g_Q16);
    cudaGetSymbolAddress((void**)&K16,  g_K16);
    cudaGetSymbolAddress((void**)&V16,  g_V16);
    cudaGetSymbolAddress((void**)&Vt,   g_Vt);
    cudaGetSymbolAddress((void**)&Sc,   g_S);
    cudaGetSymbolAddress((void**)&A16,  g_A16);
    cudaGetSymbolAddress((void**)&O16,  g_O16);

    const int nInp4 = (Bb * Nn * Cc) / 4;      // 1572864
    const int nW4   = (Cc * Cc) / 4;           // 147456
    f2h<<<(nInp4 + 255) / 256, 256>>>(query, q16, nInp4);
    f2h<<<(nInp4 + 255) / 256, 256>>>(key,   k16, nInp4);
    f2h<<<(nInp4 + 255) / 256, 256>>>(value, v16, nInp4);
    f2h<<<(nW4 + 255) / 256, 256>>>(Wq, Wq16, nW4);
    f2h<<<(nW4 + 255) / 256, 256>>>(Wk, Wk16, nW4);
    f2h<<<(nW4 + 255) / 256, 256>>>(Wv, Wv16, nW4);
    f2h<<<(nW4 + 255) / 256, 256>>>(Wo, Wo16, nW4);

    dim3 blk(256);

    // Projections: [8192,768] = X16 @ W16^T  -> fp16
    dim3 gProj(Cc / 128, (Bb * Nn) / 128, 1);
    hgemm_nt<128, __half, false><<<gProj, blk>>>(q16, Wq16, Q16, Cc, Cc, Cc, Cc, 1,
                                                 0, 0, 0, 0, 0, 0, 1.0f, nullptr);
    hgemm_nt<128, __half, false><<<gProj, blk>>>(k16, Wk16, K16, Cc, Cc, Cc, Cc, 1,
                                                 0, 0, 0, 0, 0, 0, 1.0f, nullptr);
    hgemm_nt<128, __half, false><<<gProj, blk>>>(v16, Wv16, V16, Cc, Cc, Cc, Cc, 1,
                                                 0, 0, 0, 0, 0, 0, 1.0f, nullptr);

    // Vt[b][c][s] = V16[b][s][c]
    transpose_v<<<dim3(Cc / 32, Ss / 32, Bb), dim3(32, 8)>>>(V16, Vt);

    // scores = SCALE * Qh @ Kh^T  (per (b,h): 1024x1024x64) -> fp32
    dim3 gQK(Ss / 128, Nn / 128, Bb * Hh_);
    hgemm_nt<128, float, false><<<gQK, blk>>>(Q16, K16, Sc, Dd, Cc, Cc, Ss, Hh_,
        (long long)Nn * Cc, (long long)Dd,
        (long long)Ss * Cc, (long long)Dd,
        (long long)Hh_ * Nn * Ss, (long long)Nn * Ss,
        SCALEF, nullptr);

    // softmax rows
    softmax_rows<<<Bb * Hh_ * Nn, blk>>>(Sc, aw, log_attn, A16);

    // O = attn16 @ Vh (NT vs Vt): per (b,h): 1024x64x1024 -> fp16
    dim3 gAV(1, Nn / 128, Bb * Hh_);
    hgemm_nt<64, __half, false><<<gAV, blk>>>(A16, Vt, O16, Ss, Ss, Ss, Cc, Hh_,
        (long long)Hh_ * Nn * Ss, (long long)Nn * Ss,
        (long long)Cc * Ss, (long long)Dd * Ss,
        (long long)Nn * Cc, (long long)Dd,
        1.0f, nullptr);

    // out = O16 @ Wo16^T + bo -> fp32
    hgemm_nt<128, float, true><<<gProj, blk>>>(O16, Wo16, out, Cc, Cc, Cc, Cc, 1,
        0, 0, 0, 0, 0, 0, 1.0f, bo);
}

// round 4
// speedup vs baseline: 5.0051x; 1.0993x over previous
#include <cuda_runtime.h>
#include <cuda_fp16.h>
#include <cstdint>
#include <math.h>

// Problem dims
#define Bb 8
#define Nn 1024
#define Ss 1024
#define Cc 768
#define Hh_ 12
#define Dd 64
#define SCALEF 0.125f

// ---------------------------------------------------------------------------
// Scratch (static __device__ — allocation-free per harness rules)
// ---------------------------------------------------------------------------
__device__ __half g_q16[(long long)Bb * Nn * Cc];
__device__ __half g_k16[(long long)Bb * Ss * Cc];
__device__ __half g_v16[(long long)Bb * Ss * Cc];
__device__ __half g_Wq16[Cc * Cc];
__device__ __half g_Wk16[Cc * Cc];
__device__ __half g_Wv16[Cc * Cc];
__device__ __half g_Wo16[Cc * Cc];
__device__ __half g_Q16[(long long)Bb * Nn * Cc];   // pre-scaled by 0.125
__device__ __half g_K16[(long long)Bb * Ss * Cc];
__device__ __half g_V16[(long long)Bb * Ss * Cc];
__device__ __half g_Vt[(long long)Bb * Cc * Ss];    // [B][C][S]
__device__ __half g_O16[(long long)Bb * Nn * Cc];   // head outputs

// ---------------------------------------------------------------------------
// PTX helpers
// ---------------------------------------------------------------------------
__device__ __forceinline__ unsigned s2u32(const void* p) {
    return (unsigned)__cvta_generic_to_shared(p);
}
__device__ __forceinline__ void ldsm4(unsigned* r, unsigned addr) {
    asm volatile("ldmatrix.sync.aligned.m8n8.x4.shared.b16 {%0,%1,%2,%3}, [%4];"
                 : "=r"(r[0]), "=r"(r[1]), "=r"(r[2]), "=r"(r[3]) : "r"(addr));
}
__device__ __forceinline__ void ldsm2(unsigned* r, unsigned addr) {
    asm volatile("ldmatrix.sync.aligned.m8n8.x2.shared.b16 {%0,%1}, [%2];"
                 : "=r"(r[0]), "=r"(r[1]) : "r"(addr));
}
__device__ __forceinline__ void mma16816(float* d, const unsigned* a, const unsigned* b) {
    asm volatile("mma.sync.aligned.m16n8k16.row.col.f32.f16.f16.f32 "
                 "{%0,%1,%2,%3}, {%4,%5,%6,%7}, {%8,%9}, {%0,%1,%2,%3};"
                 : "+f"(d[0]), "+f"(d[1]), "+f"(d[2]), "+f"(d[3])
                 : "r"(a[0]), "r"(a[1]), "r"(a[2]), "r"(a[3]), "r"(b[0]), "r"(b[1]));
}
__device__ __forceinline__ unsigned packh2(float a, float b) {
    __half2 h = __floats2half2_rn(a, b);
    return *reinterpret_cast<unsigned*>(&h);
}
__device__ __forceinline__ float quadMax(float v) {
    v = fmaxf(v, __shfl_xor_sync(0xffffffffu, v, 1));
    v = fmaxf(v, __shfl_xor_sync(0xffffffffu, v, 2));
    return v;
}
__device__ __forceinline__ float quadSum(float v) {
    v += __shfl_xor_sync(0xffffffffu, v, 1);
    v += __shfl_xor_sync(0xffffffffu, v, 2);
    return v;
}

// Epilogue pair-store overloads
__device__ __forceinline__ void store2(__half* C, long long off, float v0, float v1) {
    __half2* p = (__half2*)(C + off);
    *p = __floats2half2_rn(v0, v1);
}
__device__ __forceinline__ void store2(float* C, long long off, float v0, float v1) {
    float2* p = (float2*)(C + off);
    *p = make_float2(v0, v1);
}

// ---------------------------------------------------------------------------
// fp16 NT GEMM on tensor cores (projections + output projection).
// C[m][n] = scale * sum_k A[m][k]*B[n][k]  (+ bias[n] when BIAS)
// BM=128, BN=128, BK=32. 256 threads = 8 warps (4m x 2n).
// ---------------------------------------------------------------------------
template<typename OutT, bool BIAS>
__global__ __launch_bounds__(256)
void hgemm_nt(const __half* __restrict__ A, const __half* __restrict__ B,
              OutT* __restrict__ C, int Kdim, int lda, int ldb, int ldc,
              float scale, const float* __restrict__ bias)
{
    const int LDSW = 40;

    __shared__ alignas(16) __half As[2][128 * LDSW];
    __shared__ alignas(16) __half Bs[2][128 * LDSW];

    int m0 = blockIdx.y * 128;
    int n0 = blockIdx.x * 128;
    int tid = threadIdx.x;
    int lane = tid & 31;
    int w = tid >> 5;
    int wm = w & 3;
    int wn = w >> 2;

    int grow = tid >> 2;
    int gchk = tid & 3;
    const __half* gA0 = A + (long long)(m0 + grow) * lda + gchk * 8;
    const __half* gA1 = gA0 + 64ll * lda;
    const __half* gB0 = B + (long long)(n0 + grow) * ldb + gchk * 8;
    const __half* gB1 = gB0 + 64ll * ldb;

    uint4 ra0, ra1, rb0, rb1;
    int ssA = grow * LDSW + gchk * 8;

    int aBase = (wm * 32 + (lane & 15)) * LDSW + (lane >> 4) * 8;
    int bBase = (wn * 64 + (lane & 7)) * LDSW + ((lane >> 3) & 1) * 8;
    unsigned asu0 = s2u32(&As[0][0]);
    unsigned asu1 = s2u32(&As[1][0]);
    unsigned bsu0 = s2u32(&Bs[0][0]);
    unsigned bsu1 = s2u32(&Bs[1][0]);

    float acc[2][8][4];
    #pragma unroll
    for (int i = 0; i < 2; i++)
        #pragma unroll
        for (int j = 0; j < 8; j++) {
            acc[i][j][0] = 0.f; acc[i][j][1] = 0.f;
            acc[i][j][2] = 0.f; acc[i][j][3] = 0.f;
        }

    ra0 = *(const uint4*)(gA0);
    ra1 = *(const uint4*)(gA1);
    rb0 = *(const uint4*)(gB0);
    rb1 = *(const uint4*)(gB1);
    *(uint4*)&As[0][ssA] = ra0;
    *(uint4*)&As[0][ssA + 64 * LDSW] = ra1;
    *(uint4*)&Bs[0][ssA] = rb0;
    *(uint4*)&Bs[0][ssA + 64 * LDSW] = rb1;
    __syncthreads();

    int nk = Kdim >> 5;
    for (int kt = 0; kt < nk; kt++) {
        int cur = kt & 1;
        unsigned asu = cur ? asu1 : asu0;
        unsigned bsu = cur ? bsu1 : bsu0;
        if (kt + 1 < nk) {
            int k0 = (kt + 1) << 5;
            ra0 = *(const uint4*)(gA0 + k0);
            ra1 = *(const uint4*)(gA1 + k0);
            rb0 = *(const uint4*)(gB0 + k0);
            rb1 = *(const uint4*)(gB1 + k0);
        }
        #pragma unroll
        for (int kk = 0; kk < 2; kk++) {
            unsigned af[2][4];
            unsigned bf[8][2];
            #pragma unroll
            for (int mt = 0; mt < 2; mt++)
                ldsm4(af[mt], asu + 2u * (unsigned)(aBase + mt * 16 * LDSW + kk * 16));
            #pragma unroll
            for (int nt = 0; nt < 8; nt++)
                ldsm2(bf[nt], bsu + 2u * (unsigned)(bBase + nt * 8 * LDSW + kk * 16));
            #pragma unroll
            for (int mt = 0; mt < 2; mt++)
                #pragma unroll
                for (int nt = 0; nt < 8; nt++)
                    mma16816(acc[mt][nt], af[mt], bf[nt]);
        }
        if (kt + 1 < nk) {
            int nxt = cur ^ 1;
            __half* Asn = (__half*)&As[nxt][0];
            __half* Bsn = (__half*)&Bs[nxt][0];
            *(uint4*)&Asn[ssA] = ra0;
            *(uint4*)&Asn[ssA + 64 * LDSW] = ra1;
            *(uint4*)&Bsn[ssA] = rb0;
            *(uint4*)&Bsn[ssA + 64 * LDSW] = rb1;
            __syncthreads();
        }
    }

    #pragma unroll
    for (int mt = 0; mt < 2; mt++) {
        int r0 = m0 + wm * 32 + mt * 16 + (lane >> 2);
        #pragma unroll
        for (int nt = 0; nt < 8; nt++) {
            int c0 = n0 + wn * 64 + nt * 8 + (lane & 3) * 2;
            float v0 = acc[mt][nt][0] * scale;
            float v1 = acc[mt][nt][1] * scale;
            float v2 = acc[mt][nt][2] * scale;
            float v3 = acc[mt][nt][3] * scale;
            if (BIAS) {
                float bc0 = bias[c0];
                float bc1 = bias[c0 + 1];
                v0 += bc0; v1 += bc1; v2 += bc0; v3 += bc1;
            }
            store2(C, (long long)r0 * ldc + c0, v0, v1);
            store2(C, (long long)(r0 + 8) * ldc + c0, v2, v3);
        }
    }
}

// ---------------------------------------------------------------------------
// Fused attention: per CTA = one (b,h) and 128 query rows.
// Pass 1: online LSE over QK^T.  Pass 2: recompute scores, stream attn_weight,
// write log_attn, online softmax + PV accumulation (flash-style rescaling).
// 8 warps; warp w owns query rows [w*16, w*16+16).
// ---------------------------------------------------------------------------
__global__ __launch_bounds__(256)
void fused_attn(const __half* __restrict__ Q, const __half* __restrict__ K,
                const __half* __restrict__ Vt,
                const float* __restrict__ aw, float* __restrict__ log_attn,
                __half* __restrict__ O)
{
    const int LKW = 72;    // K/Q smem row stride (64 + 8 pad) in halves
    const int LVW = 136;   // Vt smem row stride (128 + 8 pad)

    __shared__ alignas(16) __half Ks[128 * LKW];
    __shared__ alignas(16) __half Vs[64 * LVW];

    int qblk = blockIdx.x;                 // 0..7
    int bh = blockIdx.y;                   // 0..95
    int b = bh / Hh_;
    int h = bh - b * Hh_;

    const __half* Qp = Q + ((long long)b * Nn + qblk * 128) * Cc + h * Dd;
    const __half* Kp = K + (long long)b * Ss * Cc + h * Dd;
    const __half* Vtp = Vt + ((long long)b * Cc + h * Dd) * Ss;
    const float* awp = aw + ((long long)bh * Nn + qblk * 128) * Ss;
    float* lap = log_attn + ((long long)bh * Nn + qblk * 128) * Ss;

    int tid = threadIdx.x;
    int lane = tid & 31;
    int wm = tid >> 5;

    unsigned ksu = s2u32(Ks);
    unsigned vsu = s2u32(Vs);

    // ---- load Q tile into Ks and extract A fragments ----
    {
        int r = tid >> 3;
        int cH = (tid & 7) * 8;
        #pragma unroll
        for (int i = 0; i < 4; i++) {
            int row = r + i * 32;
            *(uint4*)&Ks[row * LKW + cH] = *(const uint4*)(Qp + (long long)row * Cc + cH);
        }
    }
    __syncthreads();

    unsigned qf[4][4];
    {
        int aBase = (wm * 16 + (lane & 15)) * LKW + (lane >> 4) * 8;
        #pragma unroll
        for (int k = 0; k < 4; k++)
            ldsm4(qf[k], ksu + 2u * (unsigned)(aBase + k * 16));
    }
    __syncthreads();

    int bBaseK = (lane & 7) * LKW + ((lane >> 3) & 1) * 8;
    int bBaseV = (lane & 7) * LVW + ((lane >> 3) & 1) * 8;

    // ================= PASS 1: LSE =================
    float m1[2] = { -INFINITY, -INFINITY };
    float s1[2] = { 0.f, 0.f };

    for (int c = 0; c < 8; c++) {
        // load K chunk
        {
            int r = tid >> 3;
            int cH = (tid & 7) * 8;
            #pragma unroll
            for (int i = 0; i < 4; i++) {
                int row = r + i * 32;
                *(uint4*)&Ks[row * LKW + cH] =
                    *(const uint4*)(Kp + (long long)(c * 128 + row) * Cc + cH);
            }
        }
        __syncthreads();

        float sacc[16][4];
        #pragma unroll
        for (int nt = 0; nt < 16; nt++) {
            sacc[nt][0] = 0.f; sacc[nt][1] = 0.f;
            sacc[nt][2] = 0.f; sacc[nt][3] = 0.f;
        }
        #pragma unroll
        for (int kk = 0; kk < 4; kk++) {
            #pragma unroll
            for (int nt = 0; nt < 16; nt++) {
                unsigned bf[2];
                ldsm2(bf, ksu + 2u * (unsigned)(bBaseK + nt * 8 * LKW + kk * 16));
                mma16816(sacc[nt], qf[kk], bf);
            }
        }
        __syncthreads();

        #pragma unroll
        for (int hf = 0; hf < 2; hf++) {
            float cm = -INFINITY;
            #pragma unroll
            for (int nt = 0; nt < 16; nt++)
                cm = fmaxf(cm, fmaxf(sacc[nt][2 * hf], sacc[nt][2 * hf + 1]));
            cm = quadMax(cm);
            float nm = fmaxf(m1[hf], cm);
            float cs = 0.f;
            #pragma unroll
            for (int nt = 0; nt < 16; nt++)
                cs += __expf(sacc[nt][2 * hf] - nm) + __expf(sacc[nt][2 * hf + 1] - nm);
            cs = quadSum(cs);
            s1[hf] = s1[hf] * __expf(m1[hf] - nm) + cs;
            m1[hf] = nm;
        }
    }

    float lse[2];
    lse[0] = m1[0] + __logf(s1[0]);
    lse[1] = m1[1] + __logf(s1[1]);

    // ================= PASS 2: logits + PV =================
    float m2[2] = { -INFINITY, -INFINITY };
    float s2[2] = { 0.f, 0.f };
    float oacc[8][4];
    #pragma unroll
    for (int nd = 0; nd < 8; nd++) {
        oacc[nd][0] = 0.f; oacc[nd][1] = 0.f;
        oacc[nd][2] = 0.f; oacc[nd][3] = 0.f;
    }

    int rowL0 = wm * 16 + (lane >> 2);        // local query row (half 0)
    int colQ = (lane & 3) * 2;

    for (int c = 0; c < 8; c++) {
        // load K chunk + V chunk
        {
            int r = tid >> 3;
            int cH = (tid & 7) * 8;
            #pragma unroll
            for (int i = 0; i < 4; i++) {
                int row = r + i * 32;
                *(uint4*)&Ks[row * LKW + cH] =
                    *(const uint4*)(Kp + (long long)(c * 128 + row) * Cc + cH);
            }
            int dv = tid >> 4;
            int sH = (tid & 15) * 8;
            #pragma unroll
            for (int i = 0; i < 4; i++) {
                int row = dv + i * 16;
                *(uint4*)&Vs[row * LVW + sH] =
                    *(const uint4*)(Vtp + (long long)row * Ss + c * 128 + sH);
            }
        }
        __syncthreads();

        float sacc[16][4];
        #pragma unroll
        for (int nt = 0; nt < 16; nt++) {
            sacc[nt][0] = 0.f; sacc[nt][1] = 0.f;
            sacc[nt][2] = 0.f; sacc[nt][3] = 0.f;
        }
        #pragma unroll
        for (int kk = 0; kk < 4; kk++) {
            #pragma unroll
            for (int nt = 0; nt < 16; nt++) {
                unsigned bf[2];
                ldsm2(bf, ksu + 2u * (unsigned)(bBaseK + nt * 8 * LKW + kk * 16));
                mma16816(sacc[nt], qf[kk], bf);
            }
        }

        // logits: g = aw + s - lse ; write log_attn ; track chunk max
        float cm2[2] = { -INFINITY, -INFINITY };
        #pragma unroll
        for (int nt = 0; nt < 16; nt++) {
            #pragma unroll
            for (int hf = 0; hf < 2; hf++) {
                long long off = (long long)(rowL0 + hf * 8) * Ss + c * 128 + nt * 8 + colQ;
                float2 w2 = *(const float2*)(awp + off);
                float g0 = w2.x + sacc[nt][2 * hf] - lse[hf];
                float g1 = w2.y + sacc[nt][2 * hf + 1] - lse[hf];
                *(float2*)(lap + off) = make_float2(g0, g1);
                sacc[nt][2 * hf] = g0;
                sacc[nt][2 * hf + 1] = g1;
                cm2[hf] = fmaxf(cm2[hf], fmaxf(g0, g1));
            }
        }

        float alpha[2];
        #pragma unroll
        for (int hf = 0; hf < 2; hf++) {
            float cm = quadMax(cm2[hf]);
            float nm = fmaxf(m2[hf], cm);
            alpha[hf] = __expf(m2[hf] - nm);
            m2[hf] = nm;
        }
        // rescale O
        #pragma unroll
        for (int nd = 0; nd < 8; nd++) {
            oacc[nd][0] *= alpha[0]; oacc[nd][1] *= alpha[0];
            oacc[nd][2] *= alpha[1]; oacc[nd][3] *= alpha[1];
        }
        // probs + partial sums
        float cs2[2] = { 0.f, 0.f };
        #pragma unroll
        for (int nt = 0; nt < 16; nt++) {
            float p0 = __expf(sacc[nt][0] - m2[0]);
            float p1 = __expf(sacc[nt][1] - m2[0]);
            float p2 = __expf(sacc[nt][2] - m2[1]);
            float p3 = __expf(sacc[nt][3] - m2[1]);
            sacc[nt][0] = p0; sacc[nt][1] = p1;
            sacc[nt][2] = p2; sacc[nt][3] = p3;
            cs2[0] += p0 + p1;
            cs2[1] += p2 + p3;
        }
        s2[0] = s2[0] * alpha[0] + quadSum(cs2[0]);
        s2[1] = s2[1] * alpha[1] + quadSum(cs2[1]);

        // PV: probs (m16 x k128) @ V (k128 x n64)
        #pragma unroll
        for (int kk = 0; kk < 8; kk++) {
            unsigned pa[4];
            pa[0] = packh2(sacc[2 * kk][0], sacc[2 * kk][1]);
            pa[1] = packh2(sacc[2 * kk][2], sacc[2 * kk][3]);
            pa[2] = packh2(sacc[2 * kk + 1][0], sacc[2 * kk + 1][1]);
            pa[3] = packh2(sacc[2 * kk + 1][2], sacc[2 * kk + 1][3]);
            #pragma unroll
            for (int nd = 0; nd < 8; nd++) {
                unsigned bf[2];
                ldsm2(bf, vsu + 2u * (unsigned)(bBaseV + nd * 8 * LVW + kk * 16));
                mma16816(oacc[nd], pa, bf);
            }
        }
        __syncthreads();
    }

    // epilogue: O row = oacc / s2
    float inv0 = 1.0f / s2[0];
    float inv1 = 1.0f / s2[1];
    int gr0 = qblk * 128 + rowL0;
    #pragma unroll
    for (int nd = 0; nd < 8; nd++) {
        int col = h * Dd + nd * 8 + colQ;
        __half* p0 = O + ((long long)b * Nn + gr0) * Cc + col;
        __half* p1 = O + ((long long)b * Nn + gr0 + 8) * Cc + col;
        *(__half2*)p0 = __floats2half2_rn(oacc[nd][0] * inv0, oacc[nd][1] * inv0);
        *(__half2*)p1 = __floats2half2_rn(oacc[nd][2] * inv1, oacc[nd][3] * inv1);
    }
}

// ---------------------------------------------------------------------------
// fp32 -> fp16 conversion
// ---------------------------------------------------------------------------
__global__ __launch_bounds__(256)
void f2h(const float* __restrict__ in, __half* __restrict__ out, int n4)
{
    int i = blockIdx.x * 256 + threadIdx.x;
    if (i >= n4) return;
    float4 v = ((const float4*)in)[i];
    __half2* o = (__half2*)out + 2 * i;
    o[0] = __floats2half2_rn(v.x, v.y);
    o[1] = __floats2half2_rn(v.z, v.w);
}

// ---------------------------------------------------------------------------
// Transpose V16 [B][S][C] -> Vt [B][C][S]
// ---------------------------------------------------------------------------
__global__ __launch_bounds__(256)
void transpose_v(const __half* __restrict__ in, __half* __restrict__ out)
{
    __shared__ __half tile[32][33];
    int b = blockIdx.z;
    int c0 = blockIdx.x * 32;
    int s0 = blockIdx.y * 32;
    int tx = threadIdx.x;
    int ty = threadIdx.y;
    const __half* ip = in + (long long)b * Ss * Cc;
    __half* op = out + (long long)b * Cc * Ss;
    #pragma unroll
    for (int j = 0; j < 32; j += 8)
        tile[ty + j][tx] = ip[(long long)(s0 + ty + j) * Cc + c0 + tx];
    __syncthreads();
    #pragma unroll
    for (int j = 0; j < 32; j += 8)
        op[(long long)(c0 + ty + j) * Ss + s0 + tx] = tile[tx][ty + j];
}

// ---------------------------------------------------------------------------
extern "C" void kernel_launch(void* const* d_in, const int* in_sizes, int n_in,
                              void* d_out, int out_size)
{
    const float* query = (const float*)d_in[0];
    const float* key   = (const float*)d_in[1];
    const float* value = (const float*)d_in[2];
    const float* aw    = (const float*)d_in[3];
    const float* Wq    = (const float*)d_in[4];
    const float* Wk    = (const float*)d_in[5];
    const float* Wv    = (const float*)d_in[6];
    const float* Wo    = (const float*)d_in[7];
    const float* bo    = (const float*)d_in[8];

    float* out = (float*)d_out;                               // [B,N,C]
    float* log_attn = out + (long long)Bb * Nn * Cc;          // [B,H,N,S]

    __half *q16, *k16, *v16, *Wq16, *Wk16, *Wv16, *Wo16;
    __half *Q16, *K16, *V16, *Vt, *O16;
    cudaGetSymbolAddress((void**)&q16,  g_q16);
    cudaGetSymbolAddress((void**)&k16,  g_k16);
    cudaGetSymbolAddress((void**)&v16,  g_v16);
    cudaGetSymbolAddress((void**)&Wq16, g_Wq16);
    cudaGetSymbolAddress((void**)&Wk16, g_Wk16);
    cudaGetSymbolAddress((void**)&Wv16, g_Wv16);
    cudaGetSymbolAddress((void**)&Wo16, g_Wo16);
    cudaGetSymbolAddress((void**)&Q16,  g_Q16);
    cudaGetSymbolAddress((void**)&K16,  g_K16);
    cudaGetSymbolAddress((void**)&V16,  g_V16);
    cudaGetSymbolAddress((void**)&Vt,   g_Vt);
    cudaGetSymbolAddress((void**)&O16,  g_O16);

    const int nInp4 = (Bb * Nn * Cc) / 4;
    const int nW4   = (Cc * Cc) / 4;
    f2h<<<(nInp4 + 255) / 256, 256>>>(query, q16, nInp4);
    f2h<<<(nInp4 + 255) / 256, 256>>>(key,   k16, nInp4);
    f2h<<<(nInp4 + 255) / 256, 256>>>(value, v16, nInp4);
    f2h<<<(nW4 + 255) / 256, 256>>>(Wq, Wq16, nW4);
    f2h<<<(nW4 + 255) / 256, 256>>>(Wk, Wk16, nW4);
    f2h<<<(nW4 + 255) / 256, 256>>>(Wv, Wv16, nW4);
    f2h<<<(nW4 + 255) / 256, 256>>>(Wo, Wo16, nW4);

    dim3 blk(256);
    dim3 gProj(Cc / 128, (Bb * Nn) / 128, 1);

    // Projections (Q pre-scaled by SCALE, exact power of two)
    hgemm_nt<__half, false><<<gProj, blk>>>(q16, Wq16, Q16, Cc, Cc, Cc, Cc,
                                            SCALEF, nullptr);
    hgemm_nt<__half, false><<<gProj, blk>>>(k16, Wk16, K16, Cc, Cc, Cc, Cc,
                                            1.0f, nullptr);
    hgemm_nt<__half, false><<<gProj, blk>>>(v16, Wv16, V16, Cc, Cc, Cc, Cc,
                                            1.0f, nullptr);

    // Vt[b][c][s] = V16[b][s][c]
    transpose_v<<<dim3(Cc / 32, Ss / 32, Bb), dim3(32, 8)>>>(V16, Vt);

    // Fused attention: scores never hit DRAM
    fused_attn<<<dim3(Nn / 128, Bb * Hh_), blk>>>(Q16, K16, Vt, aw, log_attn, O16);

    // out = O16 @ Wo16^T + bo
    hgemm_nt<float, true><<<gProj, blk>>>(O16, Wo16, out, Cc, Cc, Cc, Cc,
                                          1.0f, bo);
}